// round 1
// baseline (speedup 1.0000x reference)
#include <cuda_runtime.h>
#include <cuda_bf16.h>

// Problem: B=64, C=1, T=1024, N=512.
// corr[b] = normalized column-centered Gram matrix of x[b,0] (T x N).
// BN stage is a per-batch affine transform -> provably cancels in correlation.
//
// G[n,m]   = sum_t x[t,n]*x[t,m] - T*mu[n]*mu[m]
// corr     = clip(G[n,m] * invd[n] * invd[m], -1, 1),  invd = rsqrt(G[n,n])

#define BB 64
#define TT 1024
#define NN 512

__device__ float g_mu[BB * NN];
__device__ float g_invd[BB * NN];

// ---------------------------------------------------------------------------
// Kernel 1: per-(batch, column) sum and sum-of-squares -> mu, invd
// Coalesced: adjacent threads = adjacent columns.
// ---------------------------------------------------------------------------
__global__ void col_stats_kernel(const float* __restrict__ x) {
    int b = blockIdx.y;
    int n = blockIdx.x * blockDim.x + threadIdx.x;
    const float* p = x + (size_t)b * TT * NN + n;
    float s = 0.f, s2 = 0.f;
#pragma unroll 8
    for (int t = 0; t < TT; ++t) {
        float v = p[(size_t)t * NN];
        s += v;
        s2 = fmaf(v, v, s2);
    }
    float mu = s * (1.0f / TT);
    float Gnn = s2 - s * mu;  // = s2 - T*mu^2
    g_mu[b * NN + n] = mu;
    g_invd[b * NN + n] = rsqrtf(fmaxf(Gnn, 1e-30f));
}

// ---------------------------------------------------------------------------
// Kernel 2: batched SYRK over upper-triangular 64x64 tile pairs + epilogue.
// 256 threads, 4x4 microtile per thread, K-tile = 16.
// ---------------------------------------------------------------------------
#define TILE 64
#define KT 16
#define NTILES (NN / TILE)                      // 8
#define NPAIRS (NTILES * (NTILES + 1) / 2)      // 36

__global__ __launch_bounds__(256) void syrk_corr_kernel(
    const float* __restrict__ x, float* __restrict__ out) {
    int b = blockIdx.y;
    // linear pair index -> (i, j) with i <= j
    int p = blockIdx.x;
    int i = 0, rem = p;
    while (rem >= NTILES - i) { rem -= NTILES - i; ++i; }
    int j = i + rem;
    int ni0 = i * TILE;
    int nj0 = j * TILE;

    __shared__ float As[KT][TILE];
    __shared__ float Bs[KT][TILE];

    int tid = threadIdx.x;
    int tx = tid & 15;        // -> n (row of output)
    int ty = tid >> 4;        // -> m (col of output)
    int lk = tid >> 4;        // loader: k row 0..15
    int ln = (tid & 15) * 4;  // loader: 4 consecutive columns

    const float* xb = x + (size_t)b * TT * NN;

    float acc[4][4] = {};

    for (int t0 = 0; t0 < TT; t0 += KT) {
        const float* row = xb + (size_t)(t0 + lk) * NN;
        float4 a4 = *(const float4*)(row + ni0 + ln);
        float4 b4 = *(const float4*)(row + nj0 + ln);
        __syncthreads();  // previous iteration's shared reads done
        *(float4*)&As[lk][ln] = a4;
        *(float4*)&Bs[lk][ln] = b4;
        __syncthreads();
#pragma unroll
        for (int kk = 0; kk < KT; ++kk) {
            float av[4], bv[4];
            *(float4*)av = *(const float4*)&As[kk][tx * 4];
            *(float4*)bv = *(const float4*)&Bs[kk][ty * 4];
#pragma unroll
            for (int aa = 0; aa < 4; ++aa)
#pragma unroll
                for (int cc = 0; cc < 4; ++cc)
                    acc[aa][cc] = fmaf(av[aa], bv[cc], acc[aa][cc]);
        }
    }

    // epilogue: mean correction, normalize, clip, mirrored writes
    float mun[4], mum[4], idn[4], idm[4];
#pragma unroll
    for (int aa = 0; aa < 4; ++aa) {
        int n = ni0 + tx * 4 + aa;
        mun[aa] = g_mu[b * NN + n];
        idn[aa] = g_invd[b * NN + n];
    }
#pragma unroll
    for (int cc = 0; cc < 4; ++cc) {
        int m = nj0 + ty * 4 + cc;
        mum[cc] = g_mu[b * NN + m];
        idm[cc] = g_invd[b * NN + m];
    }

    float* ob = out + (size_t)b * NN * NN;
#pragma unroll
    for (int aa = 0; aa < 4; ++aa) {
#pragma unroll
        for (int cc = 0; cc < 4; ++cc) {
            int n = ni0 + tx * 4 + aa;
            int m = nj0 + ty * 4 + cc;
            float G = acc[aa][cc] - (float)TT * mun[aa] * mum[cc];
            float c = G * idn[aa] * idm[cc];
            c = fminf(1.0f, fmaxf(-1.0f, c));
            ob[(size_t)n * NN + m] = c;
            ob[(size_t)m * NN + n] = c;
        }
    }
}

// ---------------------------------------------------------------------------
extern "C" void kernel_launch(void* const* d_in, const int* in_sizes, int n_in,
                              void* d_out, int out_size) {
    const float* x = (const float*)d_in[0];
    float* out = (float*)d_out;

    {
        dim3 grid(NN / 256, BB);
        col_stats_kernel<<<grid, 256>>>(x);
    }
    {
        dim3 grid(NPAIRS, BB);
        syrk_corr_kernel<<<grid, 256>>>(x, out);
    }
}

// round 2
// speedup vs baseline: 2.0222x; 2.0222x over previous
#include <cuda_runtime.h>
#include <cuda_bf16.h>
#include <cstdint>

// Problem: B=64, C=1, T=1024, N=512.
// corr[b] = normalized column-centered Gram of x[b,0] (T x N).
// BN stage is a per-batch affine transform -> cancels exactly in correlation.
//
// G[n,m] = sum_t x[t,n]*x[t,m] - T*mu[n]*mu[m]
// corr   = clip(G[n,m]*invd[n]*invd[m], -1, 1),  invd = rsqrt(G[n,n])
//
// Tensor-core path: split each fp32 into bf16 hi (exact top 16 bits) + bf16 lo
// (rounded residual). G ~= Ahi*Bhi^T + Ahi*Blo^T + Alo*Bhi^T  (3 mma passes).

#define BB 64
#define TT 1024
#define NN 512
#define NT 4            // 512 / 128 tiles
#define NPAIRS_TC 10    // upper-triangular tile pairs
#define BK 32           // K-chunk
#define PITCH 136       // bf16 elements per smem row (conflict-free)

__device__ float g_mu[BB * NN];
__device__ float g_invd[BB * NN];

// ---------------------------------------------------------------------------
// Kernel 1: per-(batch, column) sum / sum-of-squares -> mu, invd
// ---------------------------------------------------------------------------
__global__ void col_stats_kernel(const float* __restrict__ x) {
    int b = blockIdx.y;
    int n = blockIdx.x * blockDim.x + threadIdx.x;
    const float* p = x + (size_t)b * TT * NN + n;
    float s = 0.f, s2 = 0.f;
#pragma unroll 8
    for (int t = 0; t < TT; ++t) {
        float v = p[(size_t)t * NN];
        s += v;
        s2 = fmaf(v, v, s2);
    }
    float mu = s * (1.0f / TT);
    float Gnn = s2 - s * mu;
    g_mu[b * NN + n] = mu;
    g_invd[b * NN + n] = rsqrtf(fmaxf(Gnn, 1e-30f));
}

// ---------------------------------------------------------------------------
// mma / ldmatrix helpers
// ---------------------------------------------------------------------------
__device__ __forceinline__ void ldsm4t(uint32_t addr, uint32_t& r0, uint32_t& r1,
                                       uint32_t& r2, uint32_t& r3) {
    asm volatile(
        "ldmatrix.sync.aligned.m8n8.x4.trans.shared.b16 {%0,%1,%2,%3}, [%4];"
        : "=r"(r0), "=r"(r1), "=r"(r2), "=r"(r3)
        : "r"(addr));
}

__device__ __forceinline__ void mma_bf16(float* d, const uint32_t* a,
                                         const uint32_t* b) {
    asm volatile(
        "mma.sync.aligned.m16n8k16.row.col.f32.bf16.bf16.f32 "
        "{%0,%1,%2,%3},{%4,%5,%6,%7},{%8,%9},{%0,%1,%2,%3};"
        : "+f"(d[0]), "+f"(d[1]), "+f"(d[2]), "+f"(d[3])
        : "r"(a[0]), "r"(a[1]), "r"(a[2]), "r"(a[3]), "r"(b[0]), "r"(b[1]));
}

// Split 4 fp32 into (hi, lo) bf16x4, store 8B each into shared.
__device__ __forceinline__ void split_store(float4 v, __nv_bfloat16* hi,
                                            __nv_bfloat16* lo) {
    uint32_t x0 = __float_as_uint(v.x), x1 = __float_as_uint(v.y);
    uint32_t x2 = __float_as_uint(v.z), x3 = __float_as_uint(v.w);
    uint32_t h01 = __byte_perm(x0, x1, 0x7632);  // {bf16(x0), bf16(x1)} truncated
    uint32_t h23 = __byte_perm(x2, x3, 0x7632);
    float l0 = v.x - __uint_as_float(x0 & 0xFFFF0000u);  // exact residual
    float l1 = v.y - __uint_as_float(x1 & 0xFFFF0000u);
    float l2 = v.z - __uint_as_float(x2 & 0xFFFF0000u);
    float l3 = v.w - __uint_as_float(x3 & 0xFFFF0000u);
    uint32_t lo01, lo23;
    asm("cvt.rn.bf16x2.f32 %0, %1, %2;" : "=r"(lo01) : "f"(l1), "f"(l0));
    asm("cvt.rn.bf16x2.f32 %0, %1, %2;" : "=r"(lo23) : "f"(l3), "f"(l2));
    *reinterpret_cast<uint2*>(hi) = make_uint2(h01, h23);
    *reinterpret_cast<uint2*>(lo) = make_uint2(lo01, lo23);
}

// ---------------------------------------------------------------------------
// Kernel 2: batched tensor-core SYRK over upper-triangular 128x128 tile pairs
// 256 threads (8 warps), warp computes 64x32 via m16n8k16 bf16 mma, 3 passes.
// SMEM layout [k][n] with pitch 136 bf16 -> conflict-free STS and ldmatrix.
// ---------------------------------------------------------------------------
__global__ __launch_bounds__(256) void syrk_corr_tc(
    const float* __restrict__ x, float* __restrict__ out) {
    __shared__ __nv_bfloat16 Ahi[BK * PITCH], Alo[BK * PITCH];
    __shared__ __nv_bfloat16 Bhi[BK * PITCH], Blo[BK * PITCH];

    int b = blockIdx.y;
    int p = blockIdx.x;
    int i = 0, rem = p;
    while (rem >= NT - i) { rem -= NT - i; ++i; }
    int j = i + rem;
    int ni0 = i * 128;
    int nj0 = j * 128;

    const float* xb = x + (size_t)b * TT * NN;
    int tid = threadIdx.x;
    int lane = tid & 31;
    int w = tid >> 5;
    int m_off = (w & 1) * 64;   // output-row offset within tile (n side)
    int n_off = (w >> 1) * 32;  // output-col offset within tile (m side)

    uint32_t sAhi = (uint32_t)__cvta_generic_to_shared(Ahi);
    uint32_t sAlo = (uint32_t)__cvta_generic_to_shared(Alo);
    uint32_t sBhi = (uint32_t)__cvta_generic_to_shared(Bhi);
    uint32_t sBlo = (uint32_t)__cvta_generic_to_shared(Blo);

    // Per-lane static parts of ldmatrix addresses (element offsets).
    int q = lane >> 3, r7 = lane & 7;
    // A frags: q0:(r, +0) q1:(r, +8) q2:(r+8, +0) q3:(r+8, +8)
    int a_base = (r7 + (q >> 1) * 8) * PITCH + m_off + (q & 1) * 8;
    // B frags: q0:(r, +0) q1:(r+8, +0) q2:(r, +8) q3:(r+8, +8)
    int b_base = (r7 + (q & 1) * 8) * PITCH + n_off + (q >> 1) * 8;

    // Loader mapping: thread always owns the same 4 columns, rows sweep K.
    int l_n4 = (tid & 31) << 2;
    int l_k = tid >> 5;

    float acc[4][4][4] = {};

    float4 ra[4], rb[4];
    // prefetch chunk 0
#pragma unroll
    for (int qq = 0; qq < 4; ++qq) {
        const float* row = xb + (size_t)(l_k + 8 * qq) * NN;
        ra[qq] = *(const float4*)(row + ni0 + l_n4);
        rb[qq] = *(const float4*)(row + nj0 + l_n4);
    }

    for (int t0 = 0; t0 < TT; t0 += BK) {
        __syncthreads();  // mma of previous chunk done reading smem
#pragma unroll
        for (int qq = 0; qq < 4; ++qq) {
            int off = (l_k + 8 * qq) * PITCH + l_n4;
            split_store(ra[qq], &Ahi[off], &Alo[off]);
            split_store(rb[qq], &Bhi[off], &Blo[off]);
        }
        __syncthreads();

        if (t0 + BK < TT) {
#pragma unroll
            for (int qq = 0; qq < 4; ++qq) {
                const float* row = xb + (size_t)(t0 + BK + l_k + 8 * qq) * NN;
                ra[qq] = *(const float4*)(row + ni0 + l_n4);
                rb[qq] = *(const float4*)(row + nj0 + l_n4);
            }
        }

#pragma unroll
        for (int ks = 0; ks < 2; ++ks) {
            uint32_t kofs = (uint32_t)(ks * 16 * PITCH * 2);
            uint32_t a_off = (uint32_t)(a_base * 2) + kofs;
            uint32_t b_off = (uint32_t)(b_base * 2) + kofs;

            uint32_t ahi[4][4], bhi[4][2];
#pragma unroll
            for (int mt = 0; mt < 4; ++mt)
                ldsm4t(sAhi + a_off + mt * 32, ahi[mt][0], ahi[mt][1],
                       ahi[mt][2], ahi[mt][3]);
#pragma unroll
            for (int nb = 0; nb < 2; ++nb)
                ldsm4t(sBhi + b_off + nb * 32, bhi[nb * 2][0], bhi[nb * 2][1],
                       bhi[nb * 2 + 1][0], bhi[nb * 2 + 1][1]);
            // pass 1: hi * hi
#pragma unroll
            for (int mt = 0; mt < 4; ++mt)
#pragma unroll
                for (int nt = 0; nt < 4; ++nt)
                    mma_bf16(acc[mt][nt], ahi[mt], bhi[nt]);

            // pass 2: hi * lo
            uint32_t blo[4][2];
#pragma unroll
            for (int nb = 0; nb < 2; ++nb)
                ldsm4t(sBlo + b_off + nb * 32, blo[nb * 2][0], blo[nb * 2][1],
                       blo[nb * 2 + 1][0], blo[nb * 2 + 1][1]);
#pragma unroll
            for (int mt = 0; mt < 4; ++mt)
#pragma unroll
                for (int nt = 0; nt < 4; ++nt)
                    mma_bf16(acc[mt][nt], ahi[mt], blo[nt]);

            // pass 3: lo * hi
            uint32_t alo[4][4];
#pragma unroll
            for (int mt = 0; mt < 4; ++mt)
                ldsm4t(sAlo + a_off + mt * 32, alo[mt][0], alo[mt][1],
                       alo[mt][2], alo[mt][3]);
#pragma unroll
            for (int mt = 0; mt < 4; ++mt)
#pragma unroll
                for (int nt = 0; nt < 4; ++nt)
                    mma_bf16(acc[mt][nt], alo[mt], bhi[nt]);
        }
    }

    // ----------------------- epilogue -----------------------
    const float* mu_b = g_mu + b * NN;
    const float* id_b = g_invd + b * NN;
    float* ob = out + (size_t)b * NN * NN;

#pragma unroll
    for (int mt = 0; mt < 4; ++mt) {
#pragma unroll
        for (int half = 0; half < 2; ++half) {
            int R = m_off + mt * 16 + (lane >> 2) + half * 8;
            int n = ni0 + R;
            float mun = mu_b[n];
            float idn = id_b[n];
#pragma unroll
            for (int nt = 0; nt < 4; ++nt) {
                int C = n_off + nt * 8 + (lane & 3) * 2;
                int m = nj0 + C;
                float mum0 = mu_b[m], mum1 = mu_b[m + 1];
                float idm0 = id_b[m], idm1 = id_b[m + 1];
                float g0 = acc[mt][nt][half * 2 + 0] - (float)TT * mun * mum0;
                float g1 = acc[mt][nt][half * 2 + 1] - (float)TT * mun * mum1;
                float c0 = fminf(1.f, fmaxf(-1.f, g0 * idn * idm0));
                float c1 = fminf(1.f, fmaxf(-1.f, g1 * idn * idm1));
                *reinterpret_cast<float2*>(&ob[(size_t)n * NN + m]) =
                    make_float2(c0, c1);
                ob[(size_t)m * NN + n] = c0;  // mirror
                ob[(size_t)(m + 1) * NN + n] = c1;
            }
        }
    }
}

// ---------------------------------------------------------------------------
extern "C" void kernel_launch(void* const* d_in, const int* in_sizes, int n_in,
                              void* d_out, int out_size) {
    const float* x = (const float*)d_in[0];
    float* out = (float*)d_out;

    {
        dim3 grid(NN / 256, BB);
        col_stats_kernel<<<grid, 256>>>(x);
    }
    {
        dim3 grid(NPAIRS_TC, BB);
        syrk_corr_tc<<<grid, 256>>>(x, out);
    }
}

// round 4
// speedup vs baseline: 2.4728x; 1.2229x over previous
#include <cuda_runtime.h>
#include <cuda_bf16.h>
#include <cstdint>

// B=64, C=1, T=1024, N=512.
// corr[b] = normalized column-centered Gram of x[b,0] (T x N). BN cancels.
// G[n,m] = sum_t x[t,n]x[t,m] - T*mu[n]*mu[m];  corr = clip(G*invd_n*invd_m)
// Tensor path (mma.sync bf16): fp32 = hi(bf16, truncated/exact) + lo(bf16).
// G ~= Ahi*Bhi^T + Ahi*Blo^T + Alo*Bhi^T  (3 accumulating passes).

#define BB 64
#define TT 1024
#define NN 512
#define NT 4            // 512/128 tiles
#define NPAIRS_TC 10    // upper-triangular tile pairs
#define BK 32           // K-chunk
#define PITCH 136       // bf16 per smem row (conflict-free, non-pow2)
#define COMP_E (BK * PITCH)        // elements per component
#define STAGE_E (4 * COMP_E)       // Ahi,Alo,Bhi,Blo
#define DYN_B (2 * STAGE_E * 2)    // bytes, double buffered = 69632

__device__ float g_mu[BB * NN];
__device__ float g_invd[BB * NN];

// ---------------------------------------------------------------------------
// Kernel 1: column stats, T split 4-way + smem reduce (512 blocks).
// ---------------------------------------------------------------------------
__global__ __launch_bounds__(256) void col_stats_kernel(const float* __restrict__ x) {
    __shared__ float rs[256], rs2[256];
    int b = blockIdx.y;
    int n = blockIdx.x * 64 + (threadIdx.x & 63);
    int tc = threadIdx.x >> 6;
    const float* p = x + (size_t)b * TT * NN + (size_t)(tc * 256) * NN + n;
    float s = 0.f, s2 = 0.f;
#pragma unroll 8
    for (int t = 0; t < 256; ++t) {
        float v = p[(size_t)t * NN];
        s += v;
        s2 = fmaf(v, v, s2);
    }
    rs[threadIdx.x] = s;
    rs2[threadIdx.x] = s2;
    __syncthreads();
    if (threadIdx.x < 64) {
        float S = rs[threadIdx.x] + rs[threadIdx.x + 64] + rs[threadIdx.x + 128] +
                  rs[threadIdx.x + 192];
        float S2 = rs2[threadIdx.x] + rs2[threadIdx.x + 64] +
                   rs2[threadIdx.x + 128] + rs2[threadIdx.x + 192];
        float mu = S * (1.0f / TT);
        float Gnn = S2 - S * mu;
        int nn = blockIdx.x * 64 + threadIdx.x;
        g_mu[b * NN + nn] = mu;
        g_invd[b * NN + nn] = rsqrtf(fmaxf(Gnn, 1e-30f));
    }
}

// ---------------------------------------------------------------------------
// mma / ldmatrix helpers
// ---------------------------------------------------------------------------
__device__ __forceinline__ void ldsm4t(uint32_t addr, uint32_t& r0, uint32_t& r1,
                                       uint32_t& r2, uint32_t& r3) {
    asm volatile(
        "ldmatrix.sync.aligned.m8n8.x4.trans.shared.b16 {%0,%1,%2,%3}, [%4];"
        : "=r"(r0), "=r"(r1), "=r"(r2), "=r"(r3)
        : "r"(addr));
}

__device__ __forceinline__ void mma_bf16(float* d, const uint32_t* a,
                                         const uint32_t* b) {
    asm volatile(
        "mma.sync.aligned.m16n8k16.row.col.f32.bf16.bf16.f32 "
        "{%0,%1,%2,%3},{%4,%5,%6,%7},{%8,%9},{%0,%1,%2,%3};"
        : "+f"(d[0]), "+f"(d[1]), "+f"(d[2]), "+f"(d[3])
        : "r"(a[0]), "r"(a[1]), "r"(a[2]), "r"(a[3]), "r"(b[0]), "r"(b[1]));
}

// Split 4 fp32 into (hi, lo) bf16x4, store 8B each into shared.
__device__ __forceinline__ void split_store(float4 v, __nv_bfloat16* hi,
                                            __nv_bfloat16* lo) {
    uint32_t x0 = __float_as_uint(v.x), x1 = __float_as_uint(v.y);
    uint32_t x2 = __float_as_uint(v.z), x3 = __float_as_uint(v.w);
    uint32_t h01 = __byte_perm(x0, x1, 0x7632);  // truncated bf16 pair (exact hi)
    uint32_t h23 = __byte_perm(x2, x3, 0x7632);
    float l0 = v.x - __uint_as_float(x0 & 0xFFFF0000u);
    float l1 = v.y - __uint_as_float(x1 & 0xFFFF0000u);
    float l2 = v.z - __uint_as_float(x2 & 0xFFFF0000u);
    float l3 = v.w - __uint_as_float(x3 & 0xFFFF0000u);
    uint32_t lo01, lo23;
    asm("cvt.rn.bf16x2.f32 %0, %1, %2;" : "=r"(lo01) : "f"(l1), "f"(l0));
    asm("cvt.rn.bf16x2.f32 %0, %1, %2;" : "=r"(lo23) : "f"(l3), "f"(l2));
    *reinterpret_cast<uint2*>(hi) = make_uint2(h01, h23);
    *reinterpret_cast<uint2*>(lo) = make_uint2(lo01, lo23);
}

// ---------------------------------------------------------------------------
// Kernel 2: tensor-core batched SYRK over upper-tri 128x128 tile pairs.
// 8 warps, warp tile 64x32 via m16n8k16 bf16 mma, 3 passes, double-buffered
// smem K-chunks of 32, ONE __syncthreads per chunk.
// ---------------------------------------------------------------------------
__global__ __launch_bounds__(256) void syrk_corr_tc(
    const float* __restrict__ x, float* __restrict__ out) {
    extern __shared__ __nv_bfloat16 dynsm[];

    int b = blockIdx.y;
    int p = blockIdx.x;
    int i = 0, rem = p;
    while (rem >= NT - i) { rem -= NT - i; ++i; }
    int j = i + rem;
    int ni0 = i * 128;
    int nj0 = j * 128;

    const float* xb = x + (size_t)b * TT * NN;
    int tid = threadIdx.x;
    int lane = tid & 31;
    int w = tid >> 5;
    int m_off = (w & 1) * 64;   // output-row offset within tile
    int n_off = (w >> 1) * 32;  // output-col offset within tile

    // Per-lane static parts of ldmatrix addresses (element offsets).
    int q = lane >> 3, r7 = lane & 7;
    int a_base = (r7 + (q >> 1) * 8) * PITCH + m_off + (q & 1) * 8;
    int b_base = (r7 + (q & 1) * 8) * PITCH + n_off + (q >> 1) * 8;

    // Loader mapping: thread owns 4 consecutive columns, rows sweep K.
    int l_n4 = (tid & 31) << 2;
    int l_k = tid >> 5;

    float acc[4][4][4] = {};

    float4 ra[4], rb[4];
    // prefetch chunk 0
#pragma unroll
    for (int qq = 0; qq < 4; ++qq) {
        const float* row = xb + (size_t)(l_k + 8 * qq) * NN;
        ra[qq] = *(const float4*)(row + ni0 + l_n4);
        rb[qq] = *(const float4*)(row + nj0 + l_n4);
    }

    for (int c = 0; c < TT / BK; ++c) {
        __nv_bfloat16* stage = dynsm + (c & 1) * STAGE_E;
        __nv_bfloat16* Ahi = stage;
        __nv_bfloat16* Alo = stage + COMP_E;
        __nv_bfloat16* Bhi = stage + 2 * COMP_E;
        __nv_bfloat16* Blo = stage + 3 * COMP_E;

        // store prefetched chunk c into buf[c&1]
#pragma unroll
        for (int qq = 0; qq < 4; ++qq) {
            int off = (l_k + 8 * qq) * PITCH + l_n4;
            split_store(ra[qq], &Ahi[off], &Alo[off]);
            split_store(rb[qq], &Bhi[off], &Blo[off]);
        }
        __syncthreads();  // single barrier per chunk

        // prefetch chunk c+1 (LDG latency hidden under mma phase)
        if (c + 1 < TT / BK) {
            int t1 = (c + 1) * BK;
#pragma unroll
            for (int qq = 0; qq < 4; ++qq) {
                const float* row = xb + (size_t)(t1 + l_k + 8 * qq) * NN;
                ra[qq] = *(const float4*)(row + ni0 + l_n4);
                rb[qq] = *(const float4*)(row + nj0 + l_n4);
            }
        }

        uint32_t sAhi = (uint32_t)__cvta_generic_to_shared(Ahi);
        uint32_t sAlo = (uint32_t)__cvta_generic_to_shared(Alo);
        uint32_t sBhi = (uint32_t)__cvta_generic_to_shared(Bhi);
        uint32_t sBlo = (uint32_t)__cvta_generic_to_shared(Blo);

#pragma unroll
        for (int ks = 0; ks < 2; ++ks) {
            uint32_t kofs = (uint32_t)(ks * 16 * PITCH * 2);
            uint32_t a_off = (uint32_t)(a_base * 2) + kofs;
            uint32_t b_off = (uint32_t)(b_base * 2) + kofs;

            uint32_t ahi[4][4], bhi[4][2];
#pragma unroll
            for (int mt = 0; mt < 4; ++mt)
                ldsm4t(sAhi + a_off + mt * 32, ahi[mt][0], ahi[mt][1],
                       ahi[mt][2], ahi[mt][3]);
#pragma unroll
            for (int nb = 0; nb < 2; ++nb)
                ldsm4t(sBhi + b_off + nb * 32, bhi[nb * 2][0], bhi[nb * 2][1],
                       bhi[nb * 2 + 1][0], bhi[nb * 2 + 1][1]);
            // pass 1: hi * hi
#pragma unroll
            for (int mt = 0; mt < 4; ++mt)
#pragma unroll
                for (int nt = 0; nt < 4; ++nt)
                    mma_bf16(acc[mt][nt], ahi[mt], bhi[nt]);

            // pass 2: hi * lo
            uint32_t blo[4][2];
#pragma unroll
            for (int nb = 0; nb < 2; ++nb)
                ldsm4t(sBlo + b_off + nb * 32, blo[nb * 2][0], blo[nb * 2][1],
                       blo[nb * 2 + 1][0], blo[nb * 2 + 1][1]);
#pragma unroll
            for (int mt = 0; mt < 4; ++mt)
#pragma unroll
                for (int nt = 0; nt < 4; ++nt)
                    mma_bf16(acc[mt][nt], ahi[mt], blo[nt]);

            // pass 3: lo * hi
            uint32_t alo[4][4];
#pragma unroll
            for (int mt = 0; mt < 4; ++mt)
                ldsm4t(sAlo + a_off + mt * 32, alo[mt][0], alo[mt][1],
                       alo[mt][2], alo[mt][3]);
#pragma unroll
            for (int mt = 0; mt < 4; ++mt)
#pragma unroll
                for (int nt = 0; nt < 4; ++nt)
                    mma_bf16(acc[mt][nt], alo[mt], bhi[nt]);
        }
    }

    // ----------------------- epilogue -----------------------
    const float* mu_b = g_mu + b * NN;
    const float* id_b = g_invd + b * NN;
    float* ob = out + (size_t)b * NN * NN;

#pragma unroll
    for (int mt = 0; mt < 4; ++mt) {
#pragma unroll
        for (int half = 0; half < 2; ++half) {
            int R = m_off + mt * 16 + (lane >> 2) + half * 8;
            int n = ni0 + R;
            float mun = mu_b[n];
            float idn = id_b[n];
#pragma unroll
            for (int nt = 0; nt < 4; ++nt) {
                int C = n_off + nt * 8 + (lane & 3) * 2;
                int m = nj0 + C;
                float mum0 = mu_b[m], mum1 = mu_b[m + 1];
                float idm0 = id_b[m], idm1 = id_b[m + 1];
                float g0 = acc[mt][nt][half * 2 + 0] - (float)TT * mun * mum0;
                float g1 = acc[mt][nt][half * 2 + 1] - (float)TT * mun * mum1;
                float c0 = fminf(1.f, fmaxf(-1.f, g0 * idn * idm0));
                float c1 = fminf(1.f, fmaxf(-1.f, g1 * idn * idm1));
                *reinterpret_cast<float2*>(&ob[(size_t)n * NN + m]) =
                    make_float2(c0, c1);
                ob[(size_t)m * NN + n] = c0;  // mirror
                ob[(size_t)(m + 1) * NN + n] = c1;
            }
        }
    }
}

// ---------------------------------------------------------------------------
extern "C" void kernel_launch(void* const* d_in, const int* in_sizes, int n_in,
                              void* d_out, int out_size) {
    const float* x = (const float*)d_in[0];
    float* out = (float*)d_out;

    cudaFuncSetAttribute(syrk_corr_tc, cudaFuncAttributeMaxDynamicSharedMemorySize,
                         DYN_B);

    {
        dim3 grid(NN / 64, BB);
        col_stats_kernel<<<grid, 256>>>(x);
    }
    {
        dim3 grid(NPAIRS_TC, BB);
        syrk_corr_tc<<<grid, 256, DYN_B>>>(x, out);
    }
}

// round 5
// speedup vs baseline: 2.5127x; 1.0161x over previous
#include <cuda_runtime.h>
#include <cuda_bf16.h>
#include <cstdint>

// B=64, C=1, T=1024, N=512.
// corr[b] = normalized column-centered Gram of x[b,0] (T x N). BN cancels.
// G[n,m] = sum_t x[t,n]x[t,m] - T*mu[n]*mu[m];  corr = clip(G*invd_n*invd_m)
// Tensor path (mma.sync bf16): fp32 = hi(bf16 truncated, exact) + lo(bf16).
// G ~= Ahi*Bhi^T + Ahi*Blo^T + Alo*Bhi^T  (3 accumulating passes).
// R5: 512-thread CTAs (16 warps, 32x32 warp tiles) to raise warps/SMSP 2->4.

#define BB 64
#define TT 1024
#define NN 512
#define NT 4            // 512/128 tiles
#define NPAIRS_TC 10    // upper-triangular tile pairs
#define BK 32           // K-chunk
#define PITCH 136       // bf16 per smem row (conflict-free, non-pow2)
#define COMP_E (BK * PITCH)        // elements per component
#define STAGE_E (4 * COMP_E)       // Ahi,Alo,Bhi,Blo
#define DYN_B (2 * STAGE_E * 2)    // bytes, double buffered = 69632

__device__ float g_mu[BB * NN];
__device__ float g_invd[BB * NN];

// ---------------------------------------------------------------------------
// Kernel 1: column stats, T split 4-way + smem reduce (512 blocks).
// ---------------------------------------------------------------------------
__global__ __launch_bounds__(256) void col_stats_kernel(const float* __restrict__ x) {
    __shared__ float rs[256], rs2[256];
    int b = blockIdx.y;
    int n = blockIdx.x * 64 + (threadIdx.x & 63);
    int tc = threadIdx.x >> 6;
    const float* p = x + (size_t)b * TT * NN + (size_t)(tc * 256) * NN + n;
    float s = 0.f, s2 = 0.f;
#pragma unroll 8
    for (int t = 0; t < 256; ++t) {
        float v = p[(size_t)t * NN];
        s += v;
        s2 = fmaf(v, v, s2);
    }
    rs[threadIdx.x] = s;
    rs2[threadIdx.x] = s2;
    __syncthreads();
    if (threadIdx.x < 64) {
        float S = rs[threadIdx.x] + rs[threadIdx.x + 64] + rs[threadIdx.x + 128] +
                  rs[threadIdx.x + 192];
        float S2 = rs2[threadIdx.x] + rs2[threadIdx.x + 64] +
                   rs2[threadIdx.x + 128] + rs2[threadIdx.x + 192];
        float mu = S * (1.0f / TT);
        float Gnn = S2 - S * mu;
        int nn = blockIdx.x * 64 + threadIdx.x;
        g_mu[b * NN + nn] = mu;
        g_invd[b * NN + nn] = rsqrtf(fmaxf(Gnn, 1e-30f));
    }
}

// ---------------------------------------------------------------------------
// mma / ldmatrix helpers
// ---------------------------------------------------------------------------
__device__ __forceinline__ void ldsm4t(uint32_t addr, uint32_t& r0, uint32_t& r1,
                                       uint32_t& r2, uint32_t& r3) {
    asm volatile(
        "ldmatrix.sync.aligned.m8n8.x4.trans.shared.b16 {%0,%1,%2,%3}, [%4];"
        : "=r"(r0), "=r"(r1), "=r"(r2), "=r"(r3)
        : "r"(addr));
}

__device__ __forceinline__ void mma_bf16(float* d, const uint32_t* a,
                                         const uint32_t* b) {
    asm volatile(
        "mma.sync.aligned.m16n8k16.row.col.f32.bf16.bf16.f32 "
        "{%0,%1,%2,%3},{%4,%5,%6,%7},{%8,%9},{%0,%1,%2,%3};"
        : "+f"(d[0]), "+f"(d[1]), "+f"(d[2]), "+f"(d[3])
        : "r"(a[0]), "r"(a[1]), "r"(a[2]), "r"(a[3]), "r"(b[0]), "r"(b[1]));
}

// Split 4 fp32 into (hi, lo) bf16x4, store 8B each into shared.
__device__ __forceinline__ void split_store(float4 v, __nv_bfloat16* hi,
                                            __nv_bfloat16* lo) {
    uint32_t x0 = __float_as_uint(v.x), x1 = __float_as_uint(v.y);
    uint32_t x2 = __float_as_uint(v.z), x3 = __float_as_uint(v.w);
    uint32_t h01 = __byte_perm(x0, x1, 0x7632);
    uint32_t h23 = __byte_perm(x2, x3, 0x7632);
    float l0 = v.x - __uint_as_float(x0 & 0xFFFF0000u);
    float l1 = v.y - __uint_as_float(x1 & 0xFFFF0000u);
    float l2 = v.z - __uint_as_float(x2 & 0xFFFF0000u);
    float l3 = v.w - __uint_as_float(x3 & 0xFFFF0000u);
    uint32_t lo01, lo23;
    asm("cvt.rn.bf16x2.f32 %0, %1, %2;" : "=r"(lo01) : "f"(l1), "f"(l0));
    asm("cvt.rn.bf16x2.f32 %0, %1, %2;" : "=r"(lo23) : "f"(l3), "f"(l2));
    *reinterpret_cast<uint2*>(hi) = make_uint2(h01, h23);
    *reinterpret_cast<uint2*>(lo) = make_uint2(lo01, lo23);
}

// ---------------------------------------------------------------------------
// Kernel 2: tensor-core batched SYRK, 128x128 tile pairs, 512 threads.
// 16 warps, warp tile 32x32 (2 m16-frags x 4 n8-frags), 3 passes,
// double-buffered smem K-chunks of 32, one __syncthreads per chunk.
// ---------------------------------------------------------------------------
__global__ __launch_bounds__(512) void syrk_corr_tc(
    const float* __restrict__ x, float* __restrict__ out) {
    extern __shared__ __nv_bfloat16 dynsm[];

    int b = blockIdx.y;
    int p = blockIdx.x;
    int i = 0, rem = p;
    while (rem >= NT - i) { rem -= NT - i; ++i; }
    int j = i + rem;
    int ni0 = i * 128;
    int nj0 = j * 128;

    const float* xb = x + (size_t)b * TT * NN;
    int tid = threadIdx.x;
    int lane = tid & 31;
    int w = tid >> 5;
    int m_off = (w & 3) * 32;   // output-row offset within tile
    int n_off = (w >> 2) * 32;  // output-col offset within tile

    // Per-lane static parts of ldmatrix addresses (element offsets).
    int q = lane >> 3, r7 = lane & 7;
    int a_base = (r7 + (q >> 1) * 8) * PITCH + m_off + (q & 1) * 8;
    int b_base = (r7 + (q & 1) * 8) * PITCH + n_off + (q >> 1) * 8;

    // Loader mapping: thread owns 4 consecutive columns; 16 k-rows per group.
    int l_n4 = (tid & 31) << 2;
    int l_k = tid >> 5;  // 0..15

    float acc[2][4][4] = {};

    float4 ra[2], rb[2];
    // prefetch chunk 0
#pragma unroll
    for (int qq = 0; qq < 2; ++qq) {
        const float* row = xb + (size_t)(l_k + 16 * qq) * NN;
        ra[qq] = *(const float4*)(row + ni0 + l_n4);
        rb[qq] = *(const float4*)(row + nj0 + l_n4);
    }

    for (int c = 0; c < TT / BK; ++c) {
        __nv_bfloat16* stage = dynsm + (c & 1) * STAGE_E;
        __nv_bfloat16* Ahi = stage;
        __nv_bfloat16* Alo = stage + COMP_E;
        __nv_bfloat16* Bhi = stage + 2 * COMP_E;
        __nv_bfloat16* Blo = stage + 3 * COMP_E;

        // store prefetched chunk c into buf[c&1]
#pragma unroll
        for (int qq = 0; qq < 2; ++qq) {
            int off = (l_k + 16 * qq) * PITCH + l_n4;
            split_store(ra[qq], &Ahi[off], &Alo[off]);
            split_store(rb[qq], &Bhi[off], &Blo[off]);
        }
        __syncthreads();  // single barrier per chunk

        // prefetch chunk c+1 (LDG latency hidden under mma phase)
        if (c + 1 < TT / BK) {
            int t1 = (c + 1) * BK;
#pragma unroll
            for (int qq = 0; qq < 2; ++qq) {
                const float* row = xb + (size_t)(t1 + l_k + 16 * qq) * NN;
                ra[qq] = *(const float4*)(row + ni0 + l_n4);
                rb[qq] = *(const float4*)(row + nj0 + l_n4);
            }
        }

        uint32_t sAhi = (uint32_t)__cvta_generic_to_shared(Ahi);
        uint32_t sAlo = (uint32_t)__cvta_generic_to_shared(Alo);
        uint32_t sBhi = (uint32_t)__cvta_generic_to_shared(Bhi);
        uint32_t sBlo = (uint32_t)__cvta_generic_to_shared(Blo);

#pragma unroll
        for (int ks = 0; ks < 2; ++ks) {
            uint32_t kofs = (uint32_t)(ks * 16 * PITCH * 2);
            uint32_t a_off = (uint32_t)(a_base * 2) + kofs;
            uint32_t b_off = (uint32_t)(b_base * 2) + kofs;

            uint32_t ahi[2][4], bhi[4][2];
#pragma unroll
            for (int mt = 0; mt < 2; ++mt)
                ldsm4t(sAhi + a_off + mt * 32, ahi[mt][0], ahi[mt][1],
                       ahi[mt][2], ahi[mt][3]);
#pragma unroll
            for (int nb = 0; nb < 2; ++nb)
                ldsm4t(sBhi + b_off + nb * 32, bhi[nb * 2][0], bhi[nb * 2][1],
                       bhi[nb * 2 + 1][0], bhi[nb * 2 + 1][1]);
            // pass 1: hi * hi
#pragma unroll
            for (int mt = 0; mt < 2; ++mt)
#pragma unroll
                for (int nt = 0; nt < 4; ++nt)
                    mma_bf16(acc[mt][nt], ahi[mt], bhi[nt]);

            // pass 2: hi * lo
            uint32_t blo[4][2];
#pragma unroll
            for (int nb = 0; nb < 2; ++nb)
                ldsm4t(sBlo + b_off + nb * 32, blo[nb * 2][0], blo[nb * 2][1],
                       blo[nb * 2 + 1][0], blo[nb * 2 + 1][1]);
#pragma unroll
            for (int mt = 0; mt < 2; ++mt)
#pragma unroll
                for (int nt = 0; nt < 4; ++nt)
                    mma_bf16(acc[mt][nt], ahi[mt], blo[nt]);

            // pass 3: lo * hi
            uint32_t alo[2][4];
#pragma unroll
            for (int mt = 0; mt < 2; ++mt)
                ldsm4t(sAlo + a_off + mt * 32, alo[mt][0], alo[mt][1],
                       alo[mt][2], alo[mt][3]);
#pragma unroll
            for (int mt = 0; mt < 2; ++mt)
#pragma unroll
                for (int nt = 0; nt < 4; ++nt)
                    mma_bf16(acc[mt][nt], alo[mt], bhi[nt]);
        }
    }

    // ----------------------- epilogue -----------------------
    const float* mu_b = g_mu + b * NN;
    const float* id_b = g_invd + b * NN;
    float* ob = out + (size_t)b * NN * NN;

#pragma unroll
    for (int mt = 0; mt < 2; ++mt) {
#pragma unroll
        for (int half = 0; half < 2; ++half) {
            int R = m_off + mt * 16 + (lane >> 2) + half * 8;
            int n = ni0 + R;
            float mun = mu_b[n];
            float idn = id_b[n];
#pragma unroll
            for (int nt = 0; nt < 4; ++nt) {
                int C = n_off + nt * 8 + (lane & 3) * 2;
                int m = nj0 + C;
                float mum0 = mu_b[m], mum1 = mu_b[m + 1];
                float idm0 = id_b[m], idm1 = id_b[m + 1];
                float g0 = acc[mt][nt][half * 2 + 0] - (float)TT * mun * mum0;
                float g1 = acc[mt][nt][half * 2 + 1] - (float)TT * mun * mum1;
                float c0 = fminf(1.f, fmaxf(-1.f, g0 * idn * idm0));
                float c1 = fminf(1.f, fmaxf(-1.f, g1 * idn * idm1));
                *reinterpret_cast<float2*>(&ob[(size_t)n * NN + m]) =
                    make_float2(c0, c1);
                ob[(size_t)m * NN + n] = c0;  // mirror
                ob[(size_t)(m + 1) * NN + n] = c1;
            }
        }
    }
}

// ---------------------------------------------------------------------------
extern "C" void kernel_launch(void* const* d_in, const int* in_sizes, int n_in,
                              void* d_out, int out_size) {
    const float* x = (const float*)d_in[0];
    float* out = (float*)d_out;

    cudaFuncSetAttribute(syrk_corr_tc, cudaFuncAttributeMaxDynamicSharedMemorySize,
                         DYN_B);

    {
        dim3 grid(NN / 64, BB);
        col_stats_kernel<<<grid, 256>>>(x);
    }
    {
        dim3 grid(NPAIRS_TC, BB);
        syrk_corr_tc<<<grid, 512, DYN_B>>>(x, out);
    }
}

// round 6
// speedup vs baseline: 2.7322x; 1.0874x over previous
#include <cuda_runtime.h>
#include <cuda_bf16.h>
#include <cstdint>

// B=64, C=1, T=1024, N=512.
// corr[b] = normalized column-centered Gram of x[b,0] (T x N). BN cancels.
// G[n,m] = sum_t x[t,n]x[t,m] - T*mu[n]*mu[m];  corr = clip(G*invd_n*invd_m)
// Tensor path (mma.sync bf16): fp32 = hi(bf16 truncated, exact) + lo(bf16).
// G ~= Ahi*Bhi^T + Ahi*Blo^T + Alo*Bhi^T  (3 accumulating passes).
// R6: column stats FUSED into the SYRK kernel (each CTA reads its columns
// fully anyway) -> single kernel, stats kernel eliminated.

#define BB 64
#define TT 1024
#define NN 512
#define NT 4            // 512/128 tiles
#define NPAIRS_TC 10    // upper-triangular tile pairs
#define BK 32           // K-chunk
#define PITCH 136       // bf16 per smem row (conflict-free, non-pow2)
#define COMP_E (BK * PITCH)        // elements per component
#define STAGE_E (4 * COMP_E)       // Ahi,Alo,Bhi,Blo
#define DYN_B (2 * STAGE_E * 2)    // bytes, double buffered = 69632

// ---------------------------------------------------------------------------
// mma / ldmatrix helpers
// ---------------------------------------------------------------------------
__device__ __forceinline__ void ldsm4t(uint32_t addr, uint32_t& r0, uint32_t& r1,
                                       uint32_t& r2, uint32_t& r3) {
    asm volatile(
        "ldmatrix.sync.aligned.m8n8.x4.trans.shared.b16 {%0,%1,%2,%3}, [%4];"
        : "=r"(r0), "=r"(r1), "=r"(r2), "=r"(r3)
        : "r"(addr));
}

__device__ __forceinline__ void mma_bf16(float* d, const uint32_t* a,
                                         const uint32_t* b) {
    asm volatile(
        "mma.sync.aligned.m16n8k16.row.col.f32.bf16.bf16.f32 "
        "{%0,%1,%2,%3},{%4,%5,%6,%7},{%8,%9},{%0,%1,%2,%3};"
        : "+f"(d[0]), "+f"(d[1]), "+f"(d[2]), "+f"(d[3])
        : "r"(a[0]), "r"(a[1]), "r"(a[2]), "r"(a[3]), "r"(b[0]), "r"(b[1]));
}

// Split 4 fp32 into (hi, lo) bf16x4, store 8B each into shared.
__device__ __forceinline__ void split_store(float4 v, __nv_bfloat16* hi,
                                            __nv_bfloat16* lo) {
    uint32_t x0 = __float_as_uint(v.x), x1 = __float_as_uint(v.y);
    uint32_t x2 = __float_as_uint(v.z), x3 = __float_as_uint(v.w);
    uint32_t h01 = __byte_perm(x0, x1, 0x7632);
    uint32_t h23 = __byte_perm(x2, x3, 0x7632);
    float l0 = v.x - __uint_as_float(x0 & 0xFFFF0000u);
    float l1 = v.y - __uint_as_float(x1 & 0xFFFF0000u);
    float l2 = v.z - __uint_as_float(x2 & 0xFFFF0000u);
    float l3 = v.w - __uint_as_float(x3 & 0xFFFF0000u);
    uint32_t lo01, lo23;
    asm("cvt.rn.bf16x2.f32 %0, %1, %2;" : "=r"(lo01) : "f"(l1), "f"(l0));
    asm("cvt.rn.bf16x2.f32 %0, %1, %2;" : "=r"(lo23) : "f"(l3), "f"(l2));
    *reinterpret_cast<uint2*>(hi) = make_uint2(h01, h23);
    *reinterpret_cast<uint2*>(lo) = make_uint2(lo01, lo23);
}

__device__ __forceinline__ void acc_stats(float4 v, float* s, float* s2) {
    s[0] += v.x; s2[0] = fmaf(v.x, v.x, s2[0]);
    s[1] += v.y; s2[1] = fmaf(v.y, v.y, s2[1]);
    s[2] += v.z; s2[2] = fmaf(v.z, v.z, s2[2]);
    s[3] += v.w; s2[3] = fmaf(v.w, v.w, s2[3]);
}

// ---------------------------------------------------------------------------
// Fused kernel: tensor-core batched SYRK + in-CTA column stats + epilogue.
// 512 threads (16 warps), warp tile 32x32, 3 passes, double-buffered smem
// K-chunks of 32, one __syncthreads per chunk.
// ---------------------------------------------------------------------------
__global__ __launch_bounds__(512) void syrk_corr_tc(
    const float* __restrict__ x, float* __restrict__ out) {
    extern __shared__ __nv_bfloat16 dynsm[];
    __shared__ float s_muA[128], s_idA[128], s_muB[128], s_idB[128];

    int b = blockIdx.y;
    int p = blockIdx.x;
    int i = 0, rem = p;
    while (rem >= NT - i) { rem -= NT - i; ++i; }
    int j = i + rem;
    int ni0 = i * 128;
    int nj0 = j * 128;

    const float* xb = x + (size_t)b * TT * NN;
    int tid = threadIdx.x;
    int lane = tid & 31;
    int w = tid >> 5;
    int m_off = (w & 3) * 32;   // output-row offset within tile
    int n_off = (w >> 2) * 32;  // output-col offset within tile

    // Per-lane static parts of ldmatrix addresses (element offsets).
    int q = lane >> 3, r7 = lane & 7;
    int a_base = (r7 + (q >> 1) * 8) * PITCH + m_off + (q & 1) * 8;
    int b_base = (r7 + (q & 1) * 8) * PITCH + n_off + (q >> 1) * 8;

    // Loader mapping: thread owns 4 consecutive columns; rows l_k, l_k+16.
    int l_n4 = (tid & 31) << 2;
    int l_k = tid >> 5;  // 0..15

    float acc[2][4][4] = {};
    float sA[4] = {}, s2A[4] = {}, sB[4] = {}, s2B[4] = {};

    float4 ra[2], rb[2];
    // prefetch chunk 0
#pragma unroll
    for (int qq = 0; qq < 2; ++qq) {
        const float* row = xb + (size_t)(l_k + 16 * qq) * NN;
        ra[qq] = *(const float4*)(row + ni0 + l_n4);
        rb[qq] = *(const float4*)(row + nj0 + l_n4);
    }

    for (int c = 0; c < TT / BK; ++c) {
        __nv_bfloat16* stage = dynsm + (c & 1) * STAGE_E;
        __nv_bfloat16* Ahi = stage;
        __nv_bfloat16* Alo = stage + COMP_E;
        __nv_bfloat16* Bhi = stage + 2 * COMP_E;
        __nv_bfloat16* Blo = stage + 3 * COMP_E;

        // store prefetched chunk c into buf[c&1]; fold into column stats
#pragma unroll
        for (int qq = 0; qq < 2; ++qq) {
            int off = (l_k + 16 * qq) * PITCH + l_n4;
            split_store(ra[qq], &Ahi[off], &Alo[off]);
            split_store(rb[qq], &Bhi[off], &Blo[off]);
            acc_stats(ra[qq], sA, s2A);
            acc_stats(rb[qq], sB, s2B);
        }
        __syncthreads();  // single barrier per chunk

        // prefetch chunk c+1 (LDG latency hidden under mma phase)
        if (c + 1 < TT / BK) {
            int t1 = (c + 1) * BK;
#pragma unroll
            for (int qq = 0; qq < 2; ++qq) {
                const float* row = xb + (size_t)(t1 + l_k + 16 * qq) * NN;
                ra[qq] = *(const float4*)(row + ni0 + l_n4);
                rb[qq] = *(const float4*)(row + nj0 + l_n4);
            }
        }

        uint32_t sAhi = (uint32_t)__cvta_generic_to_shared(Ahi);
        uint32_t sAlo = (uint32_t)__cvta_generic_to_shared(Alo);
        uint32_t sBhi = (uint32_t)__cvta_generic_to_shared(Bhi);
        uint32_t sBlo = (uint32_t)__cvta_generic_to_shared(Blo);

#pragma unroll
        for (int ks = 0; ks < 2; ++ks) {
            uint32_t kofs = (uint32_t)(ks * 16 * PITCH * 2);
            uint32_t a_off = (uint32_t)(a_base * 2) + kofs;
            uint32_t b_off = (uint32_t)(b_base * 2) + kofs;

            uint32_t ahi[2][4], bhi[4][2];
#pragma unroll
            for (int mt = 0; mt < 2; ++mt)
                ldsm4t(sAhi + a_off + mt * 32, ahi[mt][0], ahi[mt][1],
                       ahi[mt][2], ahi[mt][3]);
#pragma unroll
            for (int nb = 0; nb < 2; ++nb)
                ldsm4t(sBhi + b_off + nb * 32, bhi[nb * 2][0], bhi[nb * 2][1],
                       bhi[nb * 2 + 1][0], bhi[nb * 2 + 1][1]);
            // pass 1: hi * hi
#pragma unroll
            for (int mt = 0; mt < 2; ++mt)
#pragma unroll
                for (int nt = 0; nt < 4; ++nt)
                    mma_bf16(acc[mt][nt], ahi[mt], bhi[nt]);

            // pass 2: hi * lo
            uint32_t blo[4][2];
#pragma unroll
            for (int nb = 0; nb < 2; ++nb)
                ldsm4t(sBlo + b_off + nb * 32, blo[nb * 2][0], blo[nb * 2][1],
                       blo[nb * 2 + 1][0], blo[nb * 2 + 1][1]);
#pragma unroll
            for (int mt = 0; mt < 2; ++mt)
#pragma unroll
                for (int nt = 0; nt < 4; ++nt)
                    mma_bf16(acc[mt][nt], ahi[mt], blo[nt]);

            // pass 3: lo * hi
            uint32_t alo[2][4];
#pragma unroll
            for (int mt = 0; mt < 2; ++mt)
                ldsm4t(sAlo + a_off + mt * 32, alo[mt][0], alo[mt][1],
                       alo[mt][2], alo[mt][3]);
#pragma unroll
            for (int mt = 0; mt < 2; ++mt)
#pragma unroll
                for (int nt = 0; nt < 4; ++nt)
                    mma_bf16(acc[mt][nt], alo[mt], bhi[nt]);
        }
    }

    // --------------- stats reduction (16 partials per column) ---------------
    __syncthreads();  // all warps done with ldsm of last chunk's smem
    float* part = (float*)dynsm;
    // layout: PA_S[16][128] @0, PA_S2 @2048, PB_S @4096, PB_S2 @6144 (floats)
    {
        int base = w * 128 + l_n4;
        *(float4*)(part + base) = *(float4*)sA;
        *(float4*)(part + 2048 + base) = *(float4*)s2A;
        *(float4*)(part + 4096 + base) = *(float4*)sB;
        *(float4*)(part + 6144 + base) = *(float4*)s2B;
    }
    __syncthreads();
    if (tid < 256) {
        int col = tid & 127;
        int grp = (tid >> 7) * 4096;  // 0 -> A, 1 -> B
        float S = 0.f, S2 = 0.f;
#pragma unroll
        for (int k = 0; k < 16; ++k) {
            S += part[grp + k * 128 + col];
            S2 += part[grp + 2048 + k * 128 + col];
        }
        float mu = S * (1.0f / TT);
        float Gnn = S2 - S * mu;
        float id = rsqrtf(fmaxf(Gnn, 1e-30f));
        if (grp == 0) { s_muA[col] = mu; s_idA[col] = id; }
        else          { s_muB[col] = mu; s_idB[col] = id; }
    }
    __syncthreads();

    // ----------------------- epilogue -----------------------
    float* ob = out + (size_t)b * NN * NN;

#pragma unroll
    for (int mt = 0; mt < 2; ++mt) {
#pragma unroll
        for (int half = 0; half < 2; ++half) {
            int R = m_off + mt * 16 + (lane >> 2) + half * 8;
            int n = ni0 + R;
            float mun = s_muA[R];
            float idn = s_idA[R];
#pragma unroll
            for (int nt = 0; nt < 4; ++nt) {
                int C = n_off + nt * 8 + (lane & 3) * 2;
                int m = nj0 + C;
                float mum0 = s_muB[C], mum1 = s_muB[C + 1];
                float idm0 = s_idB[C], idm1 = s_idB[C + 1];
                float g0 = acc[mt][nt][half * 2 + 0] - (float)TT * mun * mum0;
                float g1 = acc[mt][nt][half * 2 + 1] - (float)TT * mun * mum1;
                float c0 = fminf(1.f, fmaxf(-1.f, g0 * idn * idm0));
                float c1 = fminf(1.f, fmaxf(-1.f, g1 * idn * idm1));
                *reinterpret_cast<float2*>(&ob[(size_t)n * NN + m]) =
                    make_float2(c0, c1);
                ob[(size_t)m * NN + n] = c0;  // mirror
                ob[(size_t)(m + 1) * NN + n] = c1;
            }
        }
    }
}

// ---------------------------------------------------------------------------
extern "C" void kernel_launch(void* const* d_in, const int* in_sizes, int n_in,
                              void* d_out, int out_size) {
    const float* x = (const float*)d_in[0];
    float* out = (float*)d_out;

    cudaFuncSetAttribute(syrk_corr_tc, cudaFuncAttributeMaxDynamicSharedMemorySize,
                         DYN_B);

    dim3 grid(NPAIRS_TC, BB);
    syrk_corr_tc<<<grid, 512, DYN_B>>>(x, out);
}

// round 7
// speedup vs baseline: 2.7368x; 1.0017x over previous
#include <cuda_runtime.h>
#include <cuda_bf16.h>
#include <cstdint>

// B=64, C=1, T=1024, N=512.
// corr[b] = normalized column-centered Gram of x[b,0] (T x N). BN cancels.
// G[n,m] = sum_t x[t,n]x[t,m] - T*mu[n]*mu[m];  corr = clip(G*invd_n*invd_m)
// Tensor path (mma.sync bf16): fp32 = hi(bf16 truncated, exact) + lo(bf16).
// G ~= Ahi*Bhi^T + Ahi*Blo^T + Alo*Bhi^T  (3 accumulating passes).
// R7: 64x64 tiles (36 pairs: 10% fewer MMAs than 128-tiling), 256 threads,
// 2 CTAs/SM (wave-quant 86%->97% + cross-CTA phase overlap), fused stats,
// diagonal tiles alias B->A.

#define BB 64
#define TT 1024
#define NN 512
#define TILE 64
#define NTI 8           // 512/64
#define NPAIRS 36       // upper-triangular tile pairs
#define BK 32           // K-chunk
#define PITCH 72        // bf16 per smem row (144B, 16B-pad -> ldsm conflict-free)
#define COMP_E (BK * PITCH)        // 2304 elems per component
#define STAGE_E (4 * COMP_E)       // Ahi,Alo,Bhi,Blo
#define DYN_B (2 * STAGE_E * 2)    // bytes, double buffered = 36864

// ---------------------------------------------------------------------------
__device__ __forceinline__ void ldsm4t(uint32_t addr, uint32_t& r0, uint32_t& r1,
                                       uint32_t& r2, uint32_t& r3) {
    asm volatile(
        "ldmatrix.sync.aligned.m8n8.x4.trans.shared.b16 {%0,%1,%2,%3}, [%4];"
        : "=r"(r0), "=r"(r1), "=r"(r2), "=r"(r3)
        : "r"(addr));
}

__device__ __forceinline__ void mma_bf16(float* d, const uint32_t* a,
                                         const uint32_t* b) {
    asm volatile(
        "mma.sync.aligned.m16n8k16.row.col.f32.bf16.bf16.f32 "
        "{%0,%1,%2,%3},{%4,%5,%6,%7},{%8,%9},{%0,%1,%2,%3};"
        : "+f"(d[0]), "+f"(d[1]), "+f"(d[2]), "+f"(d[3])
        : "r"(a[0]), "r"(a[1]), "r"(a[2]), "r"(a[3]), "r"(b[0]), "r"(b[1]));
}

__device__ __forceinline__ void split_store(float4 v, __nv_bfloat16* hi,
                                            __nv_bfloat16* lo) {
    uint32_t x0 = __float_as_uint(v.x), x1 = __float_as_uint(v.y);
    uint32_t x2 = __float_as_uint(v.z), x3 = __float_as_uint(v.w);
    uint32_t h01 = __byte_perm(x0, x1, 0x7632);
    uint32_t h23 = __byte_perm(x2, x3, 0x7632);
    float l0 = v.x - __uint_as_float(x0 & 0xFFFF0000u);
    float l1 = v.y - __uint_as_float(x1 & 0xFFFF0000u);
    float l2 = v.z - __uint_as_float(x2 & 0xFFFF0000u);
    float l3 = v.w - __uint_as_float(x3 & 0xFFFF0000u);
    uint32_t lo01, lo23;
    asm("cvt.rn.bf16x2.f32 %0, %1, %2;" : "=r"(lo01) : "f"(l1), "f"(l0));
    asm("cvt.rn.bf16x2.f32 %0, %1, %2;" : "=r"(lo23) : "f"(l3), "f"(l2));
    *reinterpret_cast<uint2*>(hi) = make_uint2(h01, h23);
    *reinterpret_cast<uint2*>(lo) = make_uint2(lo01, lo23);
}

__device__ __forceinline__ void acc_stats(float4 v, float* s, float* s2) {
    s[0] += v.x; s2[0] = fmaf(v.x, v.x, s2[0]);
    s[1] += v.y; s2[1] = fmaf(v.y, v.y, s2[1]);
    s[2] += v.z; s2[2] = fmaf(v.z, v.z, s2[2]);
    s[3] += v.w; s2[3] = fmaf(v.w, v.w, s2[3]);
}

// ---------------------------------------------------------------------------
// Fused kernel: 64x64 tile pairs, 8 warps, warp tile 16x32.
// ---------------------------------------------------------------------------
__global__ __launch_bounds__(256, 2) void syrk_corr_tc(
    const float* __restrict__ x, float* __restrict__ out) {
    extern __shared__ __nv_bfloat16 dynsm[];
    __shared__ float s_muA[TILE], s_idA[TILE], s_muB[TILE], s_idB[TILE];

    int b = blockIdx.y;
    int p = blockIdx.x;
    int i = 0, rem = p;
    while (rem >= NTI - i) { rem -= NTI - i; ++i; }
    int j = i + rem;
    bool diag = (i == j);
    int ni0 = i * TILE;
    int nj0 = j * TILE;

    const float* xb = x + (size_t)b * TT * NN;
    int tid = threadIdx.x;
    int lane = tid & 31;
    int w = tid >> 5;
    int m_off = (w & 3) * 16;   // output-row offset within tile
    int n_off = (w >> 2) * 32;  // output-col offset within tile

    // ldmatrix per-lane bases (element offsets).
    int q = lane >> 3, r7 = lane & 7;
    int a_base = (r7 + (q >> 1) * 8) * PITCH + m_off + (q & 1) * 8;
    int b_base = (r7 + (q & 1) * 8) * PITCH + n_off + (q >> 1) * 8;

    // Loader: thread owns 4 consecutive columns; 16 k-rows per group.
    int l_n4 = (tid & 15) * 4;
    int l_k = tid >> 4;  // 0..15

    float acc[4][4] = {};
    float sA[4] = {}, s2A[4] = {}, sB[4] = {}, s2B[4] = {};

    const float* pa = xb + ni0 + l_n4;
    const float* pb = xb + nj0 + l_n4;

    float4 ra[2], rb[2];
#pragma unroll
    for (int qq = 0; qq < 2; ++qq) {
        ra[qq] = *(const float4*)(pa + (size_t)(l_k + 16 * qq) * NN);
        if (!diag) rb[qq] = *(const float4*)(pb + (size_t)(l_k + 16 * qq) * NN);
    }

    for (int c = 0; c < TT / BK; ++c) {
        __nv_bfloat16* stage = dynsm + (c & 1) * STAGE_E;
        __nv_bfloat16* Ahi = stage;
        __nv_bfloat16* Alo = stage + COMP_E;
        __nv_bfloat16* Bhi = stage + 2 * COMP_E;
        __nv_bfloat16* Blo = stage + 3 * COMP_E;

#pragma unroll
        for (int qq = 0; qq < 2; ++qq) {
            int off = (l_k + 16 * qq) * PITCH + l_n4;
            split_store(ra[qq], &Ahi[off], &Alo[off]);
            acc_stats(ra[qq], sA, s2A);
            if (!diag) {
                split_store(rb[qq], &Bhi[off], &Blo[off]);
                acc_stats(rb[qq], sB, s2B);
            }
        }
        __syncthreads();  // single barrier per chunk

        if (c + 1 < TT / BK) {
            int t1 = (c + 1) * BK;
#pragma unroll
            for (int qq = 0; qq < 2; ++qq) {
                ra[qq] = *(const float4*)(pa + (size_t)(t1 + l_k + 16 * qq) * NN);
                if (!diag)
                    rb[qq] = *(const float4*)(pb + (size_t)(t1 + l_k + 16 * qq) * NN);
            }
        }

        uint32_t sAhi = (uint32_t)__cvta_generic_to_shared(Ahi);
        uint32_t sAlo = (uint32_t)__cvta_generic_to_shared(Alo);
        uint32_t sBhi = diag ? sAhi : (uint32_t)__cvta_generic_to_shared(Bhi);
        uint32_t sBlo = diag ? sAlo : (uint32_t)__cvta_generic_to_shared(Blo);

#pragma unroll
        for (int ks = 0; ks < 2; ++ks) {
            uint32_t kofs = (uint32_t)(ks * 16 * PITCH * 2);
            uint32_t a_off = (uint32_t)(a_base * 2) + kofs;
            uint32_t b_off = (uint32_t)(b_base * 2) + kofs;

            uint32_t ahi[4], bhi[4][2];
            ldsm4t(sAhi + a_off, ahi[0], ahi[1], ahi[2], ahi[3]);
#pragma unroll
            for (int nb = 0; nb < 2; ++nb)
                ldsm4t(sBhi + b_off + nb * 32, bhi[nb * 2][0], bhi[nb * 2][1],
                       bhi[nb * 2 + 1][0], bhi[nb * 2 + 1][1]);
            // pass 1: hi * hi
#pragma unroll
            for (int nt = 0; nt < 4; ++nt) mma_bf16(acc[nt], ahi, bhi[nt]);

            // pass 2: hi * lo
            uint32_t blo[4][2];
#pragma unroll
            for (int nb = 0; nb < 2; ++nb)
                ldsm4t(sBlo + b_off + nb * 32, blo[nb * 2][0], blo[nb * 2][1],
                       blo[nb * 2 + 1][0], blo[nb * 2 + 1][1]);
#pragma unroll
            for (int nt = 0; nt < 4; ++nt) mma_bf16(acc[nt], ahi, blo[nt]);

            // pass 3: lo * hi
            uint32_t alo[4];
            ldsm4t(sAlo + a_off, alo[0], alo[1], alo[2], alo[3]);
#pragma unroll
            for (int nt = 0; nt < 4; ++nt) mma_bf16(acc[nt], alo, bhi[nt]);
        }
    }

    // --------------- stats reduction (16 partials per column) ---------------
    __syncthreads();
    float* part = (float*)dynsm;
    // S_A @0, S2_A @1024, S_B @2048, S2_B @3072 (floats), each [16][64]
    {
        int base = l_k * TILE + l_n4;
        *(float4*)(part + base) = *(float4*)sA;
        *(float4*)(part + 1024 + base) = *(float4*)s2A;
        if (!diag) {
            *(float4*)(part + 2048 + base) = *(float4*)sB;
            *(float4*)(part + 3072 + base) = *(float4*)s2B;
        }
    }
    __syncthreads();
    if (tid < 128) {
        int col = tid & 63;
        int isB = tid >> 6;
        int grp = (isB && !diag) ? 2048 : 0;
        float S = 0.f, S2 = 0.f;
#pragma unroll
        for (int k = 0; k < 16; ++k) {
            S += part[grp + k * TILE + col];
            S2 += part[grp + 1024 + k * TILE + col];
        }
        float mu = S * (1.0f / TT);
        float Gnn = S2 - S * mu;
        float id = rsqrtf(fmaxf(Gnn, 1e-30f));
        if (isB) { s_muB[col] = mu; s_idB[col] = id; }
        else     { s_muA[col] = mu; s_idA[col] = id; }
    }
    __syncthreads();

    // ----------------------- epilogue -----------------------
    float* ob = out + (size_t)b * NN * NN;

#pragma unroll
    for (int half = 0; half < 2; ++half) {
        int R = m_off + (lane >> 2) + half * 8;
        int n = ni0 + R;
        float mun = s_muA[R];
        float idn = s_idA[R];
#pragma unroll
        for (int nt = 0; nt < 4; ++nt) {
            int C = n_off + nt * 8 + (lane & 3) * 2;
            int m = nj0 + C;
            float mum0 = s_muB[C], mum1 = s_muB[C + 1];
            float idm0 = s_idB[C], idm1 = s_idB[C + 1];
            float g0 = acc[nt][half * 2 + 0] - (float)TT * mun * mum0;
            float g1 = acc[nt][half * 2 + 1] - (float)TT * mun * mum1;
            float c0 = fminf(1.f, fmaxf(-1.f, g0 * idn * idm0));
            float c1 = fminf(1.f, fmaxf(-1.f, g1 * idn * idm1));
            *reinterpret_cast<float2*>(&ob[(size_t)n * NN + m]) =
                make_float2(c0, c1);
            ob[(size_t)m * NN + n] = c0;  // mirror
            ob[(size_t)(m + 1) * NN + n] = c1;
        }
    }
}

// ---------------------------------------------------------------------------
extern "C" void kernel_launch(void* const* d_in, const int* in_sizes, int n_in,
                              void* d_out, int out_size) {
    const float* x = (const float*)d_in[0];
    float* out = (float*)d_out;

    cudaFuncSetAttribute(syrk_corr_tc, cudaFuncAttributeMaxDynamicSharedMemorySize,
                         DYN_B);

    dim3 grid(NPAIRS, BB);
    syrk_corr_tc<<<grid, 256, DYN_B>>>(x, out);
}